// round 16
// baseline (speedup 1.0000x reference)
#include <cuda_runtime.h>
#include <cuda_fp16.h>
#include <cstdint>

// Lorenz96, all-tensor, barrier-free (R16 = R15 + half2 conv1 epilogue).
// warp = sample end-to-end. conv1 via m16n8k8 HMMA (bias folded in K),
// gate/relu in packed f16x2, channel-interleaved hT; conv2
// D[48pad(37)][40] = W2perm[48][240] x B[240][40] via ldmatrix im2col.
// u prefetched one tile ahead; stencil head hoisted before conv2.

#define NT     256
#define GRID   296
#define X      40
#define SPT    8
#define NPOS   (SPT*X)        // 320
#define NTILES 8192           // 65536 / SPT
#define AST    248            // W2h row stride (halves)
#define HTST   56             // hT row stride (halves)
#define HT_SAMP (44*HTST)     // 2464 halves per sample
#define A1ST   24             // W1A row stride (halves)
#define UBST   8              // uB row stride (halves): k0-4 taps, k5=1, k6-7=0
#define UB_SAMP (40*UBST)     // 320 halves per sample

// smem byte offsets (16B aligned)
#define SM_W2H   0            // 23808
#define SM_HT    23808        // 39424 -> 63232
#define SM_UB    63232        // 5120  -> 68352
#define SM_W1A   68352        // 3840  -> 72192
#define SM_US    72192        // 1408  -> 73600
#define SM_B2    73600        // 192
#define SM_W3    73792        // 192
#define SM_COEFF 73984        // 72
#define SM_B3    74056        // 8
#define SM_PART  74064        // 1280 -> 75344
#define SM_TOTAL 75392

__device__ __forceinline__ uint32_t smem_u32(const void* p) {
    uint32_t a;
    asm("{ .reg .u64 t; cvta.to.shared.u64 t, %1; cvt.u32.u64 %0, t; }" : "=r"(a) : "l"(p));
    return a;
}
__device__ __forceinline__ void ldmatrix_x4(uint32_t& a0, uint32_t& a1, uint32_t& a2, uint32_t& a3,
                                            uint32_t addr) {
    asm volatile("ldmatrix.sync.aligned.m8n8.x4.shared.b16 {%0,%1,%2,%3}, [%4];"
                 : "=r"(a0), "=r"(a1), "=r"(a2), "=r"(a3) : "r"(addr));
}
__device__ __forceinline__ void ldmatrix_x2(uint32_t& a0, uint32_t& a1, uint32_t addr) {
    asm volatile("ldmatrix.sync.aligned.m8n8.x2.shared.b16 {%0,%1}, [%2];"
                 : "=r"(a0), "=r"(a1) : "r"(addr));
}
__device__ __forceinline__ void ldmatrix_x1(uint32_t& a0, uint32_t addr) {
    asm volatile("ldmatrix.sync.aligned.m8n8.x1.shared.b16 {%0}, [%1];"
                 : "=r"(a0) : "r"(addr));
}
__device__ __forceinline__ void mma16816(float* c, uint32_t a0, uint32_t a1, uint32_t a2, uint32_t a3,
                                         uint32_t b0, uint32_t b1) {
    asm volatile("mma.sync.aligned.m16n8k16.row.col.f32.f16.f16.f32 "
                 "{%0,%1,%2,%3}, {%4,%5,%6,%7}, {%8,%9}, {%0,%1,%2,%3};"
                 : "+f"(c[0]), "+f"(c[1]), "+f"(c[2]), "+f"(c[3])
                 : "r"(a0), "r"(a1), "r"(a2), "r"(a3), "r"(b0), "r"(b1));
}
__device__ __forceinline__ void mma16808(float* c, uint32_t a0, uint32_t a1, uint32_t b0) {
    asm volatile("mma.sync.aligned.m16n8k8.row.col.f32.f16.f16.f32 "
                 "{%0,%1,%2,%3}, {%4,%5}, {%6}, {%0,%1,%2,%3};"
                 : "+f"(c[0]), "+f"(c[1]), "+f"(c[2]), "+f"(c[3])
                 : "r"(a0), "r"(a1), "r"(b0));
}
__device__ __forceinline__ uint32_t pack_h2(float lo, float hi) {
    uint32_t r;
    asm("cvt.rn.f16x2.f32 %0, %1, %2;" : "=r"(r) : "f"(hi), "f"(lo));
    return r;
}
__device__ __forceinline__ uint32_t hmax2z(uint32_t a) {           // relu on f16x2
    uint32_t r;
    asm("max.f16x2 %0, %1, %2;" : "=r"(r) : "r"(a), "r"(0u));
    return r;
}
__device__ __forceinline__ uint32_t hmul2(uint32_t a, uint32_t b) {
    uint32_t r;
    asm("mul.f16x2 %0, %1, %2;" : "=r"(r) : "r"(a), "r"(b));
    return r;
}

__global__ __launch_bounds__(NT, 2)
void l96_r16_kernel(const float* __restrict__ u,  const float* __restrict__ coeff,
                    const float* __restrict__ W1, const float* __restrict__ b1,
                    const float* __restrict__ W2, const float* __restrict__ b2,
                    const float* __restrict__ W3, const float* __restrict__ b3,
                    float* __restrict__ out)
{
    extern __shared__ char sm[];
    const uint32_t smb = smem_u32(sm);
    const int tid  = threadIdx.x;
    const int wid  = tid >> 5;      // warp = sample
    const int lane = tid & 31;

    float* b2s  = (float*)(sm + SM_B2);
    float* w3s  = (float*)(sm + SM_W3);
    float* usf  = (float*)(sm + SM_US);
    float* part = (float*)(sm + SM_PART);
    __half* W2h = (__half*)(sm + SM_W2H);
    __half* W1A = (__half*)(sm + SM_W1A);
    __half* uBh = (__half*)(sm + SM_UB);
    __half* hTh = (__half*)(sm + SM_HT);

    // ---- stage weights (once) ----
    for (int i = tid; i < 48 * AST / 2; i += NT) ((uint32_t*)(sm + SM_W2H))[i] = 0;
    for (int i = tid; i < 80 * A1ST / 2; i += NT) ((uint32_t*)(sm + SM_W1A))[i] = 0;
    for (int i = tid; i < 8 * UB_SAMP / 2; i += NT) ((uint32_t*)(sm + SM_UB))[i] = 0;
    for (int i = tid; i < 48;  i += NT) {
        b2s[i] = (i < 37) ? b2[i] : 0.f;
        w3s[i] = (i < 37) ? W3[i] : 0.f;
    }
    for (int i = tid; i < 18; i += NT) ((float*)(sm + SM_COEFF))[i] = coeff[i];
    if (tid == 0) ((float*)(sm + SM_B3))[0] = b3[0];
    __syncthreads();
    // W2h[co][d*48 + cperm(ci)], cperm(ci) = 6*(ci&7) + (ci>>3)
    for (int i = tid; i < 37 * 240; i += NT) {
        int co = i / 240, k = i % 240;
        int ci = k / 5, d = k % 5;
        int cp = 6 * (ci & 7) + (ci >> 3);
        W2h[co * AST + d * 48 + cp] = __float2half(W2[i]);
    }
    // W1A[c][k]: k<5 = taps, k=5 = bias
    for (int i = tid; i < 72 * 6; i += NT) {
        int c = i / 6, k = i % 6;
        W1A[c * A1ST + k] = __float2half((k < 5) ? W1[c * 5 + k] : b1[c]);
    }
    // uB constant bias column (k=5) = 1.0 (once)
    for (int i = tid; i < 8 * 40; i += NT) {
        int s = i / 40, p = i % 40;
        uBh[s * UB_SAMP + p * UBST + 5] = __float2half(1.0f);
    }
    __syncthreads();

    // conv2 A lane addresses (3 m-tiles)
    uint32_t a_lane[3];
    #pragma unroll
    for (int mt = 0; mt < 3; mt++)
        a_lane[mt] = smb + SM_W2H +
            (uint32_t)(((mt * 16 + (lane & 15)) * AST + ((lane >> 4) << 3)) * 2);
    // conv2 B lane addresses (this warp's sample, halo row = n + d)
    const uint32_t hT_s = smb + SM_HT + (uint32_t)(wid * HT_SAMP * 2);
    const uint32_t b_lane4 = hT_s +
        (uint32_t)((((lane & 7) + ((lane >> 4) & 1) * 8) * HTST + ((lane >> 3) & 1) * 8) * 2);
    const uint32_t b_lane2 = hT_s +
        (uint32_t)(((lane & 7) * HTST + ((lane >> 3) & 1) * 8) * 2);
    // conv1 A / B lane addresses
    const uint32_t a1_lane = smb + SM_W1A + (uint32_t)(((lane & 15) * A1ST) * 2);
    const uint32_t ub_lane = smb + SM_UB +
        (uint32_t)((wid * UB_SAMP + (lane & 7) * UBST) * 2);

    const int g = lane >> 2;            // row within 8-group
    const int q = lane & 3;             // col pair

    // conv1 A fragments tile-invariant (5 m-tiles x 2 regs)
    uint32_t af[5][2];
    #pragma unroll
    for (int mt = 0; mt < 5; mt++)
        ldmatrix_x2(af[mt][0], af[mt][1], a1_lane + (uint32_t)(mt * 16 * A1ST * 2));

    // ---- u prefetch for first tile ----
    const int p0 = lane;                // position of slot 0
    const int p1 = lane + 32;           // position of slot 1 (valid if < X)
    float upf0 = 0.f, upf1 = 0.f;
    {
        size_t gs = (size_t)blockIdx.x * NPOS + wid * X;
        upf0 = u[gs + p0];
        if (p1 < X) upf1 = u[gs + p1];
    }

    for (int tile = blockIdx.x; tile < NTILES; tile += GRID) {
        const size_t gsamp = (size_t)tile * NPOS + wid * X;

        // ---- stage u from prefetch regs: fp32 halo + fp16 im2col uB ----
        {
            float* ur = usf + wid * 44;
            __half* ub = uBh + wid * UB_SAMP;
            #pragma unroll
            for (int it = 0; it < 2; it++) {
                int p = (it == 0) ? p0 : p1;
                float v = (it == 0) ? upf0 : upf1;
                if (p < X) {
                    ur[p + 2] = v;
                    if (p < 2)   ur[p + 42] = v;
                    if (p >= 38) ur[p - 38] = v;
                    __half hv = __float2half(v);
                    #pragma unroll
                    for (int d = 0; d < 5; d++) {
                        int row = p - d + 2;
                        row += (row < 0) ? X : 0;
                        row -= (row >= X) ? X : 0;
                        ub[row * UBST + d] = hv;
                    }
                }
            }
        }
        __syncwarp();

        // ---- prefetch u for next tile ----
        {
            int tn = tile + GRID;
            if (tn < NTILES) {
                size_t gn = (size_t)tn * NPOS + wid * X;
                upf0 = u[gn + p0];
                if (p1 < X) upf1 = u[gn + p1];
            }
        }

        // ---- conv1 via m16n8k8 HMMA + f16x2 gate + packed hT stores ----
        {
            __half* ht = hTh + wid * HT_SAMP;
            #pragma unroll
            for (int nt = 0; nt < 5; nt++) {
                uint32_t ub0;
                ldmatrix_x1(ub0, ub_lane + (uint32_t)(nt * 8 * UBST * 2));
                float acc1[5][4];
                #pragma unroll
                for (int mt = 0; mt < 5; mt++) {
                    #pragma unroll
                    for (int j = 0; j < 4; j++) acc1[mt][j] = 0.f;
                    mma16808(acc1[mt], af[mt][0], af[mt][1], ub0);
                }
                #pragma unroll
                for (int col = 0; col < 2; col++) {
                    int p = nt * 8 + q * 2 + col;
                    // packed pre-activations: (lo=row g, hi=row g+8) per m-tile
                    uint32_t pre0 = pack_h2(acc1[0][col], acc1[0][col + 2]); // h0,h8
                    uint32_t pre1 = pack_h2(acc1[1][col], acc1[1][col + 2]); // h16,h24pre
                    uint32_t pre2 = pack_h2(acc1[2][col], acc1[2][col + 2]); // h32pre,h40pre
                    uint32_t gt1  = pack_h2(1.0f,         acc1[3][col]);     // 1, g24
                    uint32_t gt2  = pack_h2(acc1[3][col + 2], acc1[4][col]); // g32, g40
                    uint32_t r0 = hmax2z(pre0);
                    uint32_t r1 = hmul2(hmax2z(pre1), hmax2z(gt1));
                    uint32_t r2 = hmul2(hmax2z(pre2), hmax2z(gt2));
                    uint32_t* hp = (uint32_t*)(ht + (p + 2) * HTST + 6 * g);
                    hp[0] = r0; hp[1] = r1; hp[2] = r2;
                    if (p < 2 || p >= 38) {
                        uint32_t* hq = (uint32_t*)(ht + ((p < 2) ? (p + 42) : (p - 38)) * HTST + 6 * g);
                        hq[0] = r0; hq[1] = r1; hq[2] = r2;
                    }
                }
            }
        }
        __syncwarp();

        // ---- stencil head (independent fp32, fills HMMA stall slots) ----
        float o0 = 0.f, o1 = 0.f;
        {
            const float* cf = (const float*)(sm + SM_COEFF);
            #pragma unroll
            for (int it = 0; it < 2; it++) {
                int p = (it == 0) ? p0 : p1;
                if (p < X) {
                    const float* ur = usf + wid * 44 + p;
                    float um2 = ur[0], um1 = ur[1], uc = ur[2], up1v = ur[3], up2v = ur[4];
                    float o = cf[0];
                    o = fmaf(cf[1],  um2,        o);
                    o = fmaf(cf[2],  um1,        o);
                    o = fmaf(cf[3],  uc,         o);
                    o = fmaf(cf[4],  up1v,       o);
                    o = fmaf(cf[5],  up2v,       o);
                    o = fmaf(cf[6],  um2 * um2,  o);
                    o = fmaf(cf[7],  um1 * um1,  o);
                    o = fmaf(cf[8],  uc  * uc,   o);
                    o = fmaf(cf[9],  up1v * up1v, o);
                    o = fmaf(cf[10], up2v * up2v, o);
                    o = fmaf(cf[11], um2 * um1,  o);
                    o = fmaf(cf[12], um1 * uc,   o);
                    o = fmaf(cf[13], uc  * up1v, o);
                    o = fmaf(cf[14], up1v * up2v, o);
                    o = fmaf(cf[15], um2 * uc,   o);
                    o = fmaf(cf[16], um1 * up1v, o);
                    o = fmaf(cf[17], uc  * up2v, o);
                    o += ((float*)(sm + SM_B3))[0];
                    if (it == 0) o0 = o; else o1 = o;
                }
            }
        }

        // ---- conv2 GEMM: per kt load B once, 3 A tiles, 15 HMMA ----
        float acc[3][20];
        #pragma unroll
        for (int mt = 0; mt < 3; mt++)
            #pragma unroll
            for (int j = 0; j < 20; j++) acc[mt][j] = 0.f;

        #pragma unroll
        for (int kt = 0; kt < 15; kt++) {
            const int d   = kt / 3;
            const int ci0 = (kt % 3) * 16;
            const uint32_t bofs = (uint32_t)(((d * HTST) + ci0) * 2);

            uint32_t b0, b1_, b2_, b3_;
            ldmatrix_x4(b0, b1_, b2_, b3_, b_lane4 + bofs);
            uint32_t e0, e1, e2, e3;
            ldmatrix_x4(e0, e1, e2, e3, b_lane4 + bofs + (uint32_t)(16 * HTST * 2));
            uint32_t f0, f1;
            ldmatrix_x2(f0, f1, b_lane2 + bofs + (uint32_t)(32 * HTST * 2));

            #pragma unroll
            for (int mt = 0; mt < 3; mt++) {
                uint32_t a0, a1, a2, a3;
                ldmatrix_x4(a0, a1, a2, a3, a_lane[mt] + (uint32_t)(kt * 32));
                mma16816(acc[mt] + 0,  a0, a1, a2, a3, b0, b1_);
                mma16816(acc[mt] + 4,  a0, a1, a2, a3, b2_, b3_);
                mma16816(acc[mt] + 8,  a0, a1, a2, a3, e0, e1);
                mma16816(acc[mt] + 12, a0, a1, a2, a3, e2, e3);
                mma16816(acc[mt] + 16, a0, a1, a2, a3, f0, f1);
            }
        }

        // ---- epilogue: relu(acc+b2)*W3, sum rows, shfl reduce -> part ----
        {
            float b2v[6], w3v[6];
            #pragma unroll
            for (int mt = 0; mt < 3; mt++) {
                b2v[mt*2]   = b2s[mt*16 + g];     w3v[mt*2]   = w3s[mt*16 + g];
                b2v[mt*2+1] = b2s[mt*16 + g + 8]; w3v[mt*2+1] = w3s[mt*16 + g + 8];
            }
            #pragma unroll
            for (int nt = 0; nt < 5; nt++) {
                float t0 = 0.f, t1 = 0.f;
                #pragma unroll
                for (int mt = 0; mt < 3; mt++) {
                    t0 += fmaxf(acc[mt][nt*4+0] + b2v[mt*2],   0.f) * w3v[mt*2]
                        + fmaxf(acc[mt][nt*4+2] + b2v[mt*2+1], 0.f) * w3v[mt*2+1];
                    t1 += fmaxf(acc[mt][nt*4+1] + b2v[mt*2],   0.f) * w3v[mt*2]
                        + fmaxf(acc[mt][nt*4+3] + b2v[mt*2+1], 0.f) * w3v[mt*2+1];
                }
                #pragma unroll
                for (int ofs = 4; ofs <= 16; ofs <<= 1) {
                    t0 += __shfl_xor_sync(0xFFFFFFFF, t0, ofs);
                    t1 += __shfl_xor_sync(0xFFFFFFFF, t1, ofs);
                }
                if (lane < 4) {
                    part[wid * 40 + nt * 8 + lane * 2]     = t0;
                    part[wid * 40 + nt * 8 + lane * 2 + 1] = t1;
                }
            }
        }
        __syncwarp();

        // ---- final: prefolded stencil + conv partial -> out ----
        if (p0 < X) out[gsamp + p0] = o0 + part[wid * 40 + p0];
        if (p1 < X) out[gsamp + p1] = o1 + part[wid * 40 + p1];
        __syncwarp();
    }
}

extern "C" void kernel_launch(void* const* d_in, const int* in_sizes, int n_in,
                              void* d_out, int out_size)
{
    // inputs: 0:t 1:u 2:coeff 3:W1 4:b1 5:W2 6:b2 7:W3 8:b3
    const float* u     = (const float*)d_in[1];
    const float* coeff = (const float*)d_in[2];
    const float* W1    = (const float*)d_in[3];
    const float* b1    = (const float*)d_in[4];
    const float* W2    = (const float*)d_in[5];
    const float* b2    = (const float*)d_in[6];
    const float* W3    = (const float*)d_in[7];
    const float* b3    = (const float*)d_in[8];
    float* out = (float*)d_out;

    cudaFuncSetAttribute(l96_r16_kernel, cudaFuncAttributeMaxDynamicSharedMemorySize, SM_TOTAL);
    l96_r16_kernel<<<GRID, NT, SM_TOTAL>>>(u, coeff, W1, b1, W2, b2, W3, b3, out);
}

// round 17
// speedup vs baseline: 1.1288x; 1.1288x over previous
#include <cuda_runtime.h>
#include <cuda_fp16.h>
#include <cstdint>

// Lorenz96, all-tensor (R17). Warp-local flipped conv2, zero M-pad:
// warp owns 2 samples; D[80 pos][40 ch pad 37] = im2col(hT)[80][240] x W2^T[240][40],
// mt-split into passes (mt 0-2, mt 3-4) to bound regs. conv1 = R15 (m16n8k8,
// bias folded in K, channel-interleaved hT, fp32 gate). Barrier-free main loop.
// NT=128, 3 CTAs/SM.

#define NT     128
#define GRID   444
#define X      40
#define SPT    8              // samples per CTA (4 warps x 2)
#define NPOS   (SPT*X)        // 320
#define NTILES 8192           // 65536 / SPT
#define AST    248            // W2h row stride (halves)
#define HTST   56             // hT row stride (halves)
#define HT_SAMP (44*HTST)     // 2464 halves per sample
#define A1ST   24             // W1A row stride (halves)
#define UBST   8              // uB row stride (halves)
#define UB_SAMP (40*UBST)     // 320 halves per sample

// smem byte offsets (16B aligned)
#define SM_W2H   0            // 40*248*2 = 19840
#define SM_HT    19840        // 8*2464*2 = 39424 -> 59264
#define SM_UB    59264        // 8*320*2 = 5120 -> 64384
#define SM_W1A   64384        // 80*24*2 = 3840 -> 68224
#define SM_US    68224        // 8*44*4 = 1408 -> 69632
#define SM_BW    69632        // 20*16 = 320 -> 69952
#define SM_COEFF 69952        // 72 -> 70024
#define SM_B3    70024        // 8 -> 70032
#define SM_PART  70032        // 4*80*4 = 1280 -> 71312
#define SM_TOTAL 71424

__device__ __forceinline__ uint32_t smem_u32(const void* p) {
    uint32_t a;
    asm("{ .reg .u64 t; cvta.to.shared.u64 t, %1; cvt.u32.u64 %0, t; }" : "=r"(a) : "l"(p));
    return a;
}
__device__ __forceinline__ void ldmatrix_x4(uint32_t& a0, uint32_t& a1, uint32_t& a2, uint32_t& a3,
                                            uint32_t addr) {
    asm volatile("ldmatrix.sync.aligned.m8n8.x4.shared.b16 {%0,%1,%2,%3}, [%4];"
                 : "=r"(a0), "=r"(a1), "=r"(a2), "=r"(a3) : "r"(addr));
}
__device__ __forceinline__ void ldmatrix_x2(uint32_t& a0, uint32_t& a1, uint32_t addr) {
    asm volatile("ldmatrix.sync.aligned.m8n8.x2.shared.b16 {%0,%1}, [%2];"
                 : "=r"(a0), "=r"(a1) : "r"(addr));
}
__device__ __forceinline__ void ldmatrix_x1(uint32_t& a0, uint32_t addr) {
    asm volatile("ldmatrix.sync.aligned.m8n8.x1.shared.b16 {%0}, [%1];"
                 : "=r"(a0) : "r"(addr));
}
__device__ __forceinline__ void mma16816(float* c, uint32_t a0, uint32_t a1, uint32_t a2, uint32_t a3,
                                         uint32_t b0, uint32_t b1) {
    asm volatile("mma.sync.aligned.m16n8k16.row.col.f32.f16.f16.f32 "
                 "{%0,%1,%2,%3}, {%4,%5,%6,%7}, {%8,%9}, {%0,%1,%2,%3};"
                 : "+f"(c[0]), "+f"(c[1]), "+f"(c[2]), "+f"(c[3])
                 : "r"(a0), "r"(a1), "r"(a2), "r"(a3), "r"(b0), "r"(b1));
}
__device__ __forceinline__ void mma16808(float* c, uint32_t a0, uint32_t a1, uint32_t b0) {
    asm volatile("mma.sync.aligned.m16n8k8.row.col.f32.f16.f16.f32 "
                 "{%0,%1,%2,%3}, {%4,%5}, {%6}, {%0,%1,%2,%3};"
                 : "+f"(c[0]), "+f"(c[1]), "+f"(c[2]), "+f"(c[3])
                 : "r"(a0), "r"(a1), "r"(b0));
}
__device__ __forceinline__ uint32_t pack_h2(float lo, float hi) {
    uint32_t r;
    asm("cvt.rn.f16x2.f32 %0, %1, %2;" : "=r"(r) : "f"(hi), "f"(lo));
    return r;
}

// conv2 (flipped) GEMM + epilogue for NMT m-tiles starting at mt_base.
// a_base: im2col hT lane addresses per m-tile; bw_lane: W2^T frag lane address.
// Writes per-position channel sums to partp[(mt_base+m)*16 + row]. (R14-proven.)
template<int NMT>
__device__ __forceinline__ void conv2_part(const uint32_t* a_base, uint32_t bw_lane,
                                           const float4* bw, float* partp,
                                           int mt_base, int lane)
{
    float acc[NMT][20];
    #pragma unroll
    for (int m = 0; m < NMT; m++)
        #pragma unroll
        for (int j = 0; j < 20; j++) acc[m][j] = 0.f;

    #pragma unroll
    for (int kt = 0; kt < 15; kt++) {
        const int d   = kt / 3;
        const int cp0 = (kt % 3) * 16;
        const uint32_t aofs = (uint32_t)(((d * HTST) + cp0) * 2);

        uint32_t bf[5][2];
        #pragma unroll
        for (int nt = 0; nt < 5; nt++)
            ldmatrix_x2(bf[nt][0], bf[nt][1],
                        bw_lane + (uint32_t)(nt * (8 * AST * 2) + kt * 32));

        #pragma unroll
        for (int m = 0; m < NMT; m++) {
            uint32_t a0, a1, a2, a3;
            ldmatrix_x4(a0, a1, a2, a3, a_base[m] + aofs);
            #pragma unroll
            for (int nt = 0; nt < 5; nt++)
                mma16816(acc[m] + nt * 4, a0, a1, a2, a3, bf[nt][0], bf[nt][1]);
        }
    }

    const int g = lane >> 2, q = lane & 3;
    #pragma unroll
    for (int m = 0; m < NMT; m++) {
        float s0 = 0.f, s1 = 0.f;
        #pragma unroll
        for (int nt = 0; nt < 5; nt++) {
            float4 w = bw[nt * 4 + q];
            s0 += fmaxf(acc[m][nt*4+0] + w.x, 0.f) * w.z
                + fmaxf(acc[m][nt*4+1] + w.y, 0.f) * w.w;
            s1 += fmaxf(acc[m][nt*4+2] + w.x, 0.f) * w.z
                + fmaxf(acc[m][nt*4+3] + w.y, 0.f) * w.w;
        }
        s0 += __shfl_xor_sync(0xFFFFFFFF, s0, 1);
        s0 += __shfl_xor_sync(0xFFFFFFFF, s0, 2);
        s1 += __shfl_xor_sync(0xFFFFFFFF, s1, 1);
        s1 += __shfl_xor_sync(0xFFFFFFFF, s1, 2);
        if (q == 0) {
            partp[(mt_base + m) * 16 + g]     = s0;
            partp[(mt_base + m) * 16 + g + 8] = s1;
        }
    }
}

__global__ __launch_bounds__(NT, 3)
void l96_r17_kernel(const float* __restrict__ u,  const float* __restrict__ coeff,
                    const float* __restrict__ W1, const float* __restrict__ b1,
                    const float* __restrict__ W2, const float* __restrict__ b2,
                    const float* __restrict__ W3, const float* __restrict__ b3,
                    float* __restrict__ out)
{
    extern __shared__ char sm[];
    const uint32_t smb = smem_u32(sm);
    const int tid  = threadIdx.x;
    const int wid  = tid >> 5;      // warp owns samples 2*wid, 2*wid+1
    const int lane = tid & 31;

    float*  usf  = (float*)(sm + SM_US);
    float*  part = (float*)(sm + SM_PART);
    float4* bw   = (float4*)(sm + SM_BW);
    __half* W2h  = (__half*)(sm + SM_W2H);
    __half* W1A  = (__half*)(sm + SM_W1A);
    __half* uBh  = (__half*)(sm + SM_UB);
    __half* hTh  = (__half*)(sm + SM_HT);

    // ---- stage weights (once) ----
    for (int i = tid; i < 40 * AST / 2; i += NT) ((uint32_t*)(sm + SM_W2H))[i] = 0;
    for (int i = tid; i < 80 * A1ST / 2; i += NT) ((uint32_t*)(sm + SM_W1A))[i] = 0;
    for (int i = tid; i < 8 * UB_SAMP / 2; i += NT) ((uint32_t*)(sm + SM_UB))[i] = 0;
    for (int i = tid; i < 20; i += NT) {                 // bw: channels nt*8+2q, +1
        int c = (i >> 2) * 8 + (i & 3) * 2;
        float bx = (c     < 37) ? b2[c]     : 0.f;
        float by = (c + 1 < 37) ? b2[c + 1] : 0.f;
        float wz = (c     < 37) ? W3[c]     : 0.f;
        float ww = (c + 1 < 37) ? W3[c + 1] : 0.f;
        bw[i] = make_float4(bx, by, wz, ww);
    }
    for (int i = tid; i < 18; i += NT) ((float*)(sm + SM_COEFF))[i] = coeff[i];
    if (tid == 0) ((float*)(sm + SM_B3))[0] = b3[0];
    __syncthreads();
    // W2h[co][d*48 + cperm(ci)], cperm(ci) = 6*(ci&7) + (ci>>3); rows 37-39 zero
    for (int i = tid; i < 37 * 240; i += NT) {
        int co = i / 240, k = i % 240;
        int ci = k / 5, d = k % 5;
        int cp = 6 * (ci & 7) + (ci >> 3);
        W2h[co * AST + d * 48 + cp] = __float2half(W2[i]);
    }
    // W1A[c][k]: k<5 = taps, k=5 = bias (uB k5 column is 1.0)
    for (int i = tid; i < 72 * 6; i += NT) {
        int c = i / 6, k = i % 6;
        W1A[c * A1ST + k] = __float2half((k < 5) ? W1[c * 5 + k] : b1[c]);
    }
    // uB constant bias column (once)
    for (int i = tid; i < 8 * 40; i += NT) {
        int s = i / 40, p = i % 40;
        uBh[s * UB_SAMP + p * UBST + 5] = __float2half(1.0f);
    }
    __syncthreads();

    // conv2 A (im2col over this warp's 2 samples' hT) lane addresses, 5 m-tiles
    uint32_t a_base[5];
    #pragma unroll
    for (int mt = 0; mt < 5; mt++) {
        int posg = mt * 16 + (lane & 15);       // 0..79 within warp
        int s2 = posg / X, p = posg % X;
        a_base[mt] = smb + SM_HT +
            (uint32_t)(((wid * 2 + s2) * HT_SAMP + p * HTST + ((lane >> 4) << 3)) * 2);
    }
    // conv2 B (W2^T) lane address
    const uint32_t bw_lane = smb + SM_W2H +
        (uint32_t)(((lane & 7) * AST + ((lane >> 3) & 1) * 8) * 2);
    // conv1 A / B lane addresses
    const uint32_t a1_lane = smb + SM_W1A + (uint32_t)(((lane & 15) * A1ST) * 2);
    const uint32_t ub_lane0 = smb + SM_UB +
        (uint32_t)((wid * 2 * UB_SAMP + (lane & 7) * UBST) * 2);

    const int g = lane >> 2;
    const int q = lane & 3;

    // conv1 A fragments tile-invariant (5 m-tiles x 2 regs)
    uint32_t af[5][2];
    #pragma unroll
    for (int mt = 0; mt < 5; mt++)
        ldmatrix_x2(af[mt][0], af[mt][1], a1_lane + (uint32_t)(mt * 16 * A1ST * 2));

    // ---- u prefetch for first tile: 3 slots cover 80 values/warp ----
    float upf[3] = {0.f, 0.f, 0.f};
    {
        size_t gw = (size_t)blockIdx.x * NPOS + wid * 80;
        #pragma unroll
        for (int it = 0; it < 3; it++) {
            int idx = lane + it * 32;
            if (idx < 80) upf[it] = u[gw + idx];
        }
    }

    for (int tile = blockIdx.x; tile < NTILES; tile += GRID) {
        const size_t gwarp = (size_t)tile * NPOS + wid * 80;

        // ---- stage u (2 samples): fp32 halo + fp16 im2col uB ----
        #pragma unroll
        for (int it = 0; it < 3; it++) {
            int idx = lane + it * 32;
            if (idx < 80) {
                int s2 = idx / X, p = idx % X;
                float v = upf[it];
                float* ur = usf + (wid * 2 + s2) * 44;
                ur[p + 2] = v;
                if (p < 2)   ur[p + 42] = v;
                if (p >= 38) ur[p - 38] = v;
                __half hv = __float2half(v);
                __half* ub = uBh + (wid * 2 + s2) * UB_SAMP;
                #pragma unroll
                for (int d = 0; d < 5; d++) {
                    int row = p - d + 2;
                    row += (row < 0) ? X : 0;
                    row -= (row >= X) ? X : 0;
                    ub[row * UBST + d] = hv;
                }
            }
        }
        __syncwarp();

        // ---- prefetch u for next tile ----
        {
            int tn = tile + GRID;
            if (tn < NTILES) {
                size_t gn = (size_t)tn * NPOS + wid * 80;
                #pragma unroll
                for (int it = 0; it < 3; it++) {
                    int idx = lane + it * 32;
                    if (idx < 80) upf[it] = u[gn + idx];
                }
            }
        }

        // ---- conv1 via m16n8k8 HMMA + gate + packed hT stores, both samples ----
        #pragma unroll
        for (int s2 = 0; s2 < 2; s2++) {
            const uint32_t ubl = ub_lane0 + (uint32_t)(s2 * UB_SAMP * 2);
            __half* ht = hTh + (wid * 2 + s2) * HT_SAMP;
            #pragma unroll
            for (int nt = 0; nt < 5; nt++) {
                uint32_t ub0;
                ldmatrix_x1(ub0, ubl + (uint32_t)(nt * 8 * UBST * 2));
                float acc1[5][4];
                #pragma unroll
                for (int mt = 0; mt < 5; mt++) {
                    #pragma unroll
                    for (int j = 0; j < 4; j++) acc1[mt][j] = 0.f;
                    mma16808(acc1[mt], af[mt][0], af[mt][1], ub0);
                }
                #pragma unroll
                for (int col = 0; col < 2; col++) {
                    int p = nt * 8 + q * 2 + col;
                    float h0  = fmaxf(acc1[0][col],     0.f);
                    float h8  = fmaxf(acc1[0][col + 2], 0.f);
                    float h16 = fmaxf(acc1[1][col],     0.f);
                    float h24 = fmaxf(acc1[1][col + 2], 0.f)
                              * fmaxf(acc1[3][col],     0.f);
                    float h32 = fmaxf(acc1[2][col],     0.f)
                              * fmaxf(acc1[3][col + 2], 0.f);
                    float h40 = fmaxf(acc1[2][col + 2], 0.f)
                              * fmaxf(acc1[4][col],     0.f);
                    uint32_t r0 = pack_h2(h0,  h8);
                    uint32_t r1 = pack_h2(h16, h24);
                    uint32_t r2 = pack_h2(h32, h40);
                    uint32_t* hp = (uint32_t*)(ht + (p + 2) * HTST + 6 * g);
                    hp[0] = r0; hp[1] = r1; hp[2] = r2;
                    if (p < 2 || p >= 38) {
                        uint32_t* hq = (uint32_t*)(ht + ((p < 2) ? (p + 42) : (p - 38)) * HTST + 6 * g);
                        hq[0] = r0; hq[1] = r1; hq[2] = r2;
                    }
                }
            }
        }
        __syncwarp();

        // ---- stencil head (independent fp32; fills HMMA stall slots) ----
        float ost[3] = {0.f, 0.f, 0.f};
        {
            const float* cf = (const float*)(sm + SM_COEFF);
            #pragma unroll
            for (int it = 0; it < 3; it++) {
                int idx = lane + it * 32;
                if (idx < 80) {
                    int s2 = idx / X, p = idx % X;
                    const float* ur = usf + (wid * 2 + s2) * 44 + p;
                    float um2 = ur[0], um1 = ur[1], uc = ur[2], up1v = ur[3], up2v = ur[4];
                    float o = cf[0];
                    o = fmaf(cf[1],  um2,        o);
                    o = fmaf(cf[2],  um1,        o);
                    o = fmaf(cf[3],  uc,         o);
                    o = fmaf(cf[4],  up1v,       o);
                    o = fmaf(cf[5],  up2v,       o);
                    o = fmaf(cf[6],  um2 * um2,  o);
                    o = fmaf(cf[7],  um1 * um1,  o);
                    o = fmaf(cf[8],  uc  * uc,   o);
                    o = fmaf(cf[9],  up1v * up1v, o);
                    o = fmaf(cf[10], up2v * up2v, o);
                    o = fmaf(cf[11], um2 * um1,  o);
                    o = fmaf(cf[12], um1 * uc,   o);
                    o = fmaf(cf[13], uc  * up1v, o);
                    o = fmaf(cf[14], up1v * up2v, o);
                    o = fmaf(cf[15], um2 * uc,   o);
                    o = fmaf(cf[16], um1 * up1v, o);
                    o = fmaf(cf[17], uc  * up2v, o);
                    ost[it] = o + ((float*)(sm + SM_B3))[0];
                }
            }
        }

        // ---- conv2 flipped, two mt passes (reg-bounded), warp-local ----
        conv2_part<3>(a_base,     bw_lane, bw, part + wid * 80, 0, lane);
        conv2_part<2>(a_base + 3, bw_lane, bw, part + wid * 80, 3, lane);
        __syncwarp();

        // ---- final: stencil + conv partial -> out ----
        #pragma unroll
        for (int it = 0; it < 3; it++) {
            int idx = lane + it * 32;
            if (idx < 80)
                out[gwarp + idx] = ost[it] + part[wid * 80 + idx];
        }
        __syncwarp();
    }
}

extern "C" void kernel_launch(void* const* d_in, const int* in_sizes, int n_in,
                              void* d_out, int out_size)
{
    // inputs: 0:t 1:u 2:coeff 3:W1 4:b1 5:W2 6:b2 7:W3 8:b3
    const float* u     = (const float*)d_in[1];
    const float* coeff = (const float*)d_in[2];
    const float* W1    = (const float*)d_in[3];
    const float* b1    = (const float*)d_in[4];
    const float* W2    = (const float*)d_in[5];
    const float* b2    = (const float*)d_in[6];
    const float* W3    = (const float*)d_in[7];
    const float* b3    = (const float*)d_in[8];
    float* out = (float*)d_out;

    cudaFuncSetAttribute(l96_r17_kernel, cudaFuncAttributeMaxDynamicSharedMemorySize, SM_TOTAL);
    l96_r17_kernel<<<GRID, NT, SM_TOTAL>>>(u, coeff, W1, b1, W2, b2, W3, b3, out);
}